// round 1
// baseline (speedup 1.0000x reference)
#include <cuda_runtime.h>
#include <math.h>

#define Bc   8
#define Hh   8
#define Dd   512
#define HD   64
#define LNS  64
#define LS   2048
#define LSO  512
#define LQ   (LSO + LNS)   // 576
#define LK   (LS + LNS)    // 2112
#define LL   (LS + LNS)    // tokens per batch in x
#define DELTA (LK - LQ)    // 1536

// Scratch (device globals; no allocation allowed)
__device__ float g_Q[(size_t)Bc * Hh * LQ * HD];     // [B,H,LQ,64]
__device__ float g_K[(size_t)Bc * Hh * LK * HD];     // [B,H,LK,64]
__device__ float g_V[(size_t)Bc * Hh * LK * HD];     // [B,H,LK,64]
__device__ float g_attn[(size_t)Bc * LQ * Dd];       // [B,LQ,D]

// ---------------------------------------------------------------------------
// Tiled SGEMM: C[M,512] = gather(X) @ W[512,512] + bias
// Input row m -> x[( (m/bt)*Lx + tok_off + m%bt ) * 512]
// Output mode 0: Out[m*512+n] (plain)
//        mode 1: Out[((b*H + n/64)*Lout + tok_off_out + t)*64 + n%64]
// ---------------------------------------------------------------------------
__global__ void gemm_mix(const float* __restrict__ X, const float* __restrict__ W,
                         const float* __restrict__ bias, float* __restrict__ Out,
                         int bt, int tok_off, int Lx,
                         int mode, int Lout, int out_tok_off)
{
    __shared__ float As[16][65];
    __shared__ float Bs[16][68];

    const int tid = threadIdx.x;            // 256 threads
    const int m0 = blockIdx.y * 64;
    const int n0 = blockIdx.x * 64;
    const int ty = tid >> 4, tx = tid & 15; // 16x16 compute grid

    // Load mapping
    const int lr_a = tid >> 2;              // 0..63 (m within tile)
    const int kc_a = (tid & 3) << 2;        // 0,4,8,12
    const int kr_b = tid >> 4;              // 0..15
    const int nc_b = (tid & 15) << 2;       // 0..60

    const int ma = m0 + lr_a;
    const float* xrow = X + ((size_t)(ma / bt) * Lx + tok_off + (ma % bt)) * (size_t)Dd;
    const float* wptr = W + (size_t)kr_b * Dd + n0 + nc_b;

    float acc[4][4] = {};

    for (int k0 = 0; k0 < Dd; k0 += 16) {
        float4 a = *(const float4*)(xrow + k0 + kc_a);
        As[kc_a + 0][lr_a] = a.x;
        As[kc_a + 1][lr_a] = a.y;
        As[kc_a + 2][lr_a] = a.z;
        As[kc_a + 3][lr_a] = a.w;
        float4 bv = *(const float4*)(wptr + (size_t)k0 * Dd);
        Bs[kr_b][nc_b + 0] = bv.x;
        Bs[kr_b][nc_b + 1] = bv.y;
        Bs[kr_b][nc_b + 2] = bv.z;
        Bs[kr_b][nc_b + 3] = bv.w;
        __syncthreads();
        #pragma unroll
        for (int kk = 0; kk < 16; kk++) {
            float ar[4], br[4];
            #pragma unroll
            for (int i = 0; i < 4; i++) ar[i] = As[kk][ty * 4 + i];
            #pragma unroll
            for (int j = 0; j < 4; j++) br[j] = Bs[kk][tx * 4 + j];
            #pragma unroll
            for (int i = 0; i < 4; i++)
                #pragma unroll
                for (int j = 0; j < 4; j++)
                    acc[i][j] += ar[i] * br[j];
        }
        __syncthreads();
    }

    #pragma unroll
    for (int i = 0; i < 4; i++) {
        const int m = m0 + ty * 4 + i;
        const int b = m / bt, t = m % bt;
        #pragma unroll
        for (int j = 0; j < 4; j++) {
            const int n = n0 + tx * 4 + j;
            const float c = acc[i][j] + bias[n];
            if (mode == 0) {
                Out[(size_t)m * Dd + n] = c;
            } else {
                const int h = n >> 6, dd = n & 63;
                Out[(((size_t)b * Hh + h) * Lout + (out_tok_off + t)) * HD + dd] = c;
            }
        }
    }
}

// ---------------------------------------------------------------------------
// Per-token (non-shared) projection: out[b, n, :] = x[b, LS+n, :] @ nw[n] + nb[n]
// grid (64, 2), 256 threads. Each block handles one token index n and 256 out cols,
// all 8 batches (weight matrix read once).
// ---------------------------------------------------------------------------
__global__ void ns_proj(const float* __restrict__ x, const float* __restrict__ nw,
                        const float* __restrict__ nb, float* __restrict__ Out,
                        int Lout, int out_tok_off)
{
    const int n = blockIdx.x;                       // token 0..63
    const int o = blockIdx.y * 256 + threadIdx.x;   // out col 0..511

    __shared__ float xs[8][512];
    for (int i = threadIdx.x; i < 8 * 512; i += 256) {
        const int b = i >> 9, k = i & 511;
        xs[b][k] = x[((size_t)b * LL + LS + n) * Dd + k];
    }
    __syncthreads();

    float acc[8] = {};
    const float* wp = nw + (size_t)n * Dd * Dd + o;
    for (int k = 0; k < Dd; k++) {
        const float w = wp[(size_t)k * Dd];
        #pragma unroll
        for (int b = 0; b < 8; b++) acc[b] += xs[b][k] * w;
    }

    const float bias = nb[(size_t)n * Dd + o];
    const int h = o >> 6, dd = o & 63;
    const int l = out_tok_off + n;
    #pragma unroll
    for (int b = 0; b < 8; b++)
        Out[(((size_t)b * Hh + h) * Lout + l) * HD + dd] = acc[b] + bias;
}

// ---------------------------------------------------------------------------
// Flash attention, fp32. grid (LQ/32 = 18, B*H = 64), 256 threads.
// 32 query rows per block, K-tiles of 64. 8 lanes per query row.
// ---------------------------------------------------------------------------
__global__ void flash_attn(const float* __restrict__ Q, const float* __restrict__ K,
                           const float* __restrict__ V, const int* __restrict__ pad_mask,
                           float* __restrict__ Outp)
{
    const int bh = blockIdx.y;
    const int b = bh >> 3, h = bh & 7;
    const int q0 = blockIdx.x * 32;

    const float* Qp = Q + ((size_t)bh * LQ + q0) * HD;
    const float* Kp = K + (size_t)bh * LK * HD;
    const float* Vp = V + (size_t)bh * LK * HD;

    __shared__ float Qs[32][65];
    __shared__ float Ks[64][65];
    __shared__ float Vs[64][64];
    __shared__ float Ps[32][64];
    __shared__ int   pads[64];

    const int tid = threadIdx.x;
    for (int i = tid; i < 32 * 64; i += 256)
        Qs[i >> 6][i & 63] = Qp[i] * 0.125f;   // 1/sqrt(64)

    const int r = tid >> 3;       // query row within tile (0..31)
    const int g = tid & 7;        // lane group (owns keys g*8..g*8+7 and dims g*8..g*8+7)
    const int qg = q0 + r;

    float m_run = -1e30f, l_run = 0.0f;
    float acc[8] = {};

    const int jlim = q0 + 31 + DELTA;                       // max causal key in block
    const int ntiles = min(LK / 64, (jlim >> 6) + 1);

    for (int kt = 0; kt < ntiles; kt++) {
        const int k0 = kt * 64;
        __syncthreads();
        for (int i = tid; i < 64 * 64; i += 256) {
            const int rr = i >> 6, cc = i & 63;
            Ks[rr][cc] = Kp[(size_t)(k0 + rr) * HD + cc];
            Vs[rr][cc] = Vp[(size_t)(k0 + rr) * HD + cc];
        }
        if (tid < 64) {
            const int jg = k0 + tid;
            pads[tid] = (jg >= LS) ? 1 : pad_mask[(size_t)b * LS + jg];
        }
        __syncthreads();

        // scores for 8 keys owned by this lane
        float s[8] = {};
        #pragma unroll 16
        for (int k = 0; k < 64; k++) {
            const float qk = Qs[r][k];
            #pragma unroll
            for (int jj = 0; jj < 8; jj++)
                s[jj] += qk * Ks[g * 8 + jj][k];
        }
        #pragma unroll
        for (int jj = 0; jj < 8; jj++) {
            const int j = g * 8 + jj;
            const int jgl = k0 + j;
            const bool ok = (jgl <= qg + DELTA) && pads[j];
            if (!ok) s[jj] = -1e9f;
        }

        // row max across 8 values x 8 lanes
        float mx = s[0];
        #pragma unroll
        for (int jj = 1; jj < 8; jj++) mx = fmaxf(mx, s[jj]);
        mx = fmaxf(mx, __shfl_xor_sync(0xffffffffu, mx, 1));
        mx = fmaxf(mx, __shfl_xor_sync(0xffffffffu, mx, 2));
        mx = fmaxf(mx, __shfl_xor_sync(0xffffffffu, mx, 4));

        const float m_new = fmaxf(m_run, mx);
        const float corr = __expf(m_run - m_new);

        float psum = 0.0f;
        #pragma unroll
        for (int jj = 0; jj < 8; jj++) {
            const float p = __expf(s[jj] - m_new);
            psum += p;
            Ps[r][g * 8 + jj] = p;
        }
        psum += __shfl_xor_sync(0xffffffffu, psum, 1);
        psum += __shfl_xor_sync(0xffffffffu, psum, 2);
        psum += __shfl_xor_sync(0xffffffffu, psum, 4);

        l_run = l_run * corr + psum;
        m_run = m_new;
        #pragma unroll
        for (int d = 0; d < 8; d++) acc[d] *= corr;

        __syncwarp();   // Ps writers/readers for a row are in the same warp

        #pragma unroll 16
        for (int j = 0; j < 64; j++) {
            const float p = Ps[r][j];
            #pragma unroll
            for (int d = 0; d < 8; d++)
                acc[d] += p * Vs[j][g * 8 + d];
        }
    }

    const float inv = (l_run > 0.0f) ? (1.0f / l_run) : 0.0f;
    float* op = Outp + ((size_t)b * LQ + qg) * Dd + h * HD + g * 8;
    #pragma unroll
    for (int d = 0; d < 8; d++) op[d] = acc[d] * inv;
}

// ---------------------------------------------------------------------------
extern "C" void kernel_launch(void* const* d_in, const int* in_sizes, int n_in,
                              void* d_out, int out_size)
{
    const float* x        = (const float*)d_in[0];
    const int*   pad_mask = (const int*)  d_in[1];
    // d_in[2] = L_s (2048), d_in[3] = L_s_out (512): fixed, hard-coded.
    const float* wq_sw = (const float*)d_in[4];
    const float* wq_sb = (const float*)d_in[5];
    const float* wq_nw = (const float*)d_in[6];
    const float* wq_nb = (const float*)d_in[7];
    const float* wk_sw = (const float*)d_in[8];
    const float* wk_sb = (const float*)d_in[9];
    const float* wk_nw = (const float*)d_in[10];
    const float* wk_nb = (const float*)d_in[11];
    const float* wv_sw = (const float*)d_in[12];
    const float* wv_sb = (const float*)d_in[13];
    const float* wv_nw = (const float*)d_in[14];
    const float* wv_nb = (const float*)d_in[15];
    const float* out_w = (const float*)d_in[16];
    const float* out_b = (const float*)d_in[17];
    float* out = (float*)d_out;

    float *pQ, *pK, *pV, *pA;
    cudaGetSymbolAddress((void**)&pQ, g_Q);
    cudaGetSymbolAddress((void**)&pK, g_K);
    cudaGetSymbolAddress((void**)&pV, g_V);
    cudaGetSymbolAddress((void**)&pA, g_attn);

    // Shared-weight projections
    // K: rows = B*2048, x tokens [0,2048), out K layout [B,H,2112,64] tokens [0,2048)
    gemm_mix<<<dim3(8, (Bc * LS) / 64), 256>>>(x, wk_sw, wk_sb, pK,
                                               LS, 0, LL, 1, LK, 0);
    // V
    gemm_mix<<<dim3(8, (Bc * LS) / 64), 256>>>(x, wv_sw, wv_sb, pV,
                                               LS, 0, LL, 1, LK, 0);
    // Q: rows = B*512, x tokens [1536,2048), out Q layout [B,H,576,64] tokens [0,512)
    gemm_mix<<<dim3(8, (Bc * LSO) / 64), 256>>>(x, wq_sw, wq_sb, pQ,
                                                LSO, LS - LSO, LL, 1, LQ, 0);

    // Non-shared (per-token) projections
    ns_proj<<<dim3(64, 2), 256>>>(x, wq_nw, wq_nb, pQ, LQ, LSO);
    ns_proj<<<dim3(64, 2), 256>>>(x, wk_nw, wk_nb, pK, LK, LS);
    ns_proj<<<dim3(64, 2), 256>>>(x, wv_nw, wv_nb, pV, LK, LS);

    // Attention -> g_attn [B, LQ, D]
    flash_attn<<<dim3(LQ / 32, Bc * Hh), 256>>>(pQ, pK, pV, pad_mask, pA);

    // Output projection -> d_out [B*LQ, D]
    gemm_mix<<<dim3(8, (Bc * LQ) / 64), 256>>>(pA, out_w, out_b, out,
                                               LQ, 0, LQ, 0, 0, 0);
}

// round 2
// speedup vs baseline: 3.2401x; 3.2401x over previous
#include <cuda_runtime.h>
#include <math.h>

#define Bc   8
#define Hh   8
#define Dd   512
#define HD   64
#define LNS  64
#define LS   2048
#define LSO  512
#define LQ   (LSO + LNS)   // 576
#define LK   (LS + LNS)    // 2112
#define LL   (LS + LNS)    // tokens per batch in x
#define DELTA (LK - LQ)    // 1536

// Scratch (device globals; no allocation allowed)
__device__ float g_Q[(size_t)Bc * Hh * LQ * HD];     // [B,H,LQ,64]
__device__ float g_K[(size_t)Bc * Hh * LK * HD];     // [B,H,LK,64]
__device__ float g_V[(size_t)Bc * Hh * LK * HD];     // [B,H,LK,64]
__device__ float g_attn[(size_t)Bc * LQ * Dd];       // [B,LQ,D]

// ---------------------------------------------------------------------------
// tf32 helpers
// ---------------------------------------------------------------------------
__device__ __forceinline__ unsigned f2tf(float f) {
    unsigned u;
    asm("cvt.rna.tf32.f32 %0, %1;" : "=r"(u) : "f"(f));
    return u;
}

__device__ __forceinline__ void mma8(float* c, const unsigned* a, const unsigned* b) {
    asm volatile(
        "mma.sync.aligned.m16n8k8.row.col.f32.tf32.tf32.f32 "
        "{%0,%1,%2,%3},{%4,%5,%6,%7},{%8,%9},{%0,%1,%2,%3};\n"
        : "+f"(c[0]), "+f"(c[1]), "+f"(c[2]), "+f"(c[3])
        : "r"(a[0]), "r"(a[1]), "r"(a[2]), "r"(a[3]), "r"(b[0]), "r"(b[1]));
}

// ---------------------------------------------------------------------------
// Split-tf32 GEMM: C[M,512] = gather(X) @ W[512,512] + bias   (fp32-accurate)
// Tile 128(M) x 64(N) x 16(K), 256 threads (8 warps, 4x2 warp grid).
// Input row m -> x[( (m/bt)*Lx + tok_off + m%bt ) * 512]
// mode 0: Out[m*512+n];  mode 1: Out[((b*H + n/64)*Lout + out_tok_off + t)*64 + n%64]
// ---------------------------------------------------------------------------
__global__ __launch_bounds__(256) void gemm_tc(
    const float* __restrict__ X, const float* __restrict__ W,
    const float* __restrict__ bias, float* __restrict__ Out,
    int bt, int tok_off, int Lx, int mode, int Lout, int out_tok_off)
{
    __shared__ unsigned Ah[16][136], Al[16][136];   // [k][m], conflict-free frag reads
    __shared__ unsigned Bh[16][72],  Bl[16][72];    // [k][n]

    const int tid  = threadIdx.x;
    const int lane = tid & 31, warp = tid >> 5;
    const int wm = warp >> 1, wn = warp & 1;
    const int g  = lane >> 2, tg = lane & 3;
    const int m0 = blockIdx.y << 7, n0 = blockIdx.x << 6;

    // A loader: rows m0+(tid&127), k chunk by (tid>>7)
    const int am = tid & 127;
    const int ak = (tid >> 7) << 2;
    const int gm = m0 + am;
    const float* xrow = X + ((size_t)(gm / bt) * Lx + tok_off + (gm % bt)) * (size_t)Dd;

    // B loader
    const int bk = tid >> 4;
    const int bn = (tid & 15) << 2;
    const float* wptr = W + (size_t)bk * Dd + n0 + bn;

    float acc[2][4][4];
    #pragma unroll
    for (int a = 0; a < 2; a++)
        #pragma unroll
        for (int b = 0; b < 4; b++)
            #pragma unroll
            for (int c = 0; c < 4; c++) acc[a][b][c] = 0.f;

    for (int k0 = 0; k0 < Dd; k0 += 16) {
        #pragma unroll
        for (int hh = 0; hh < 2; hh++) {
            float4 v = *(const float4*)(xrow + k0 + ak + hh * 8);
            float fv[4] = {v.x, v.y, v.z, v.w};
            #pragma unroll
            for (int j = 0; j < 4; j++) {
                unsigned hi = f2tf(fv[j]);
                Ah[ak + hh * 8 + j][am] = hi;
                Al[ak + hh * 8 + j][am] = f2tf(fv[j] - __uint_as_float(hi));
            }
        }
        {
            float4 v = *(const float4*)(wptr + (size_t)k0 * Dd);
            float fv[4] = {v.x, v.y, v.z, v.w};
            #pragma unroll
            for (int j = 0; j < 4; j++) {
                unsigned hi = f2tf(fv[j]);
                Bh[bk][bn + j] = hi;
                Bl[bk][bn + j] = f2tf(fv[j] - __uint_as_float(hi));
            }
        }
        __syncthreads();

        #pragma unroll
        for (int ks = 0; ks < 2; ks++) {
            unsigned ah[2][4], al[2][4], bhf[4][2], blf[4][2];
            #pragma unroll
            for (int mt = 0; mt < 2; mt++) {
                const int mr = wm * 32 + mt * 16;
                ah[mt][0] = Ah[ks * 8 + tg][mr + g];
                ah[mt][1] = Ah[ks * 8 + tg][mr + g + 8];
                ah[mt][2] = Ah[ks * 8 + tg + 4][mr + g];
                ah[mt][3] = Ah[ks * 8 + tg + 4][mr + g + 8];
                al[mt][0] = Al[ks * 8 + tg][mr + g];
                al[mt][1] = Al[ks * 8 + tg][mr + g + 8];
                al[mt][2] = Al[ks * 8 + tg + 4][mr + g];
                al[mt][3] = Al[ks * 8 + tg + 4][mr + g + 8];
            }
            #pragma unroll
            for (int nt = 0; nt < 4; nt++) {
                const int nc = wn * 32 + nt * 8 + g;
                bhf[nt][0] = Bh[ks * 8 + tg][nc];
                bhf[nt][1] = Bh[ks * 8 + tg + 4][nc];
                blf[nt][0] = Bl[ks * 8 + tg][nc];
                blf[nt][1] = Bl[ks * 8 + tg + 4][nc];
            }
            #pragma unroll
            for (int mt = 0; mt < 2; mt++)
                #pragma unroll
                for (int nt = 0; nt < 4; nt++) {
                    mma8(acc[mt][nt], ah[mt], bhf[nt]);   // hi*hi
                    mma8(acc[mt][nt], al[mt], bhf[nt]);   // lo*hi
                    mma8(acc[mt][nt], ah[mt], blf[nt]);   // hi*lo
                }
        }
        __syncthreads();
    }

    // epilogue
    #pragma unroll
    for (int mt = 0; mt < 2; mt++)
        #pragma unroll
        for (int j2 = 0; j2 < 2; j2++) {
            const int m = m0 + wm * 32 + mt * 16 + g + j2 * 8;
            const int b = m / bt, t = m % bt;
            #pragma unroll
            for (int nt = 0; nt < 4; nt++) {
                const int n = n0 + wn * 32 + nt * 8 + 2 * tg;
                const float c0 = acc[mt][nt][j2 * 2 + 0] + bias[n];
                const float c1 = acc[mt][nt][j2 * 2 + 1] + bias[n + 1];
                if (mode == 0) {
                    *(float2*)&Out[(size_t)m * Dd + n] = make_float2(c0, c1);
                } else {
                    const int h = n >> 6, dd = n & 63;
                    *(float2*)&Out[(((size_t)b * Hh + h) * Lout + out_tok_off + t) * HD + dd] =
                        make_float2(c0, c1);
                }
            }
        }
}

// ---------------------------------------------------------------------------
// Per-token projections, bandwidth-optimized.
// grid (64 tokens, 4 col-blocks of 128), 256 threads: k split 2-way in-block,
// weight loads unrolled x16 for MLP. Each weight element read exactly once.
// ---------------------------------------------------------------------------
__global__ __launch_bounds__(256) void ns_proj(
    const float* __restrict__ x, const float* __restrict__ nw,
    const float* __restrict__ nb, float* __restrict__ Out,
    int Lout, int out_tok_off)
{
    const int n   = blockIdx.x;
    const int tid = threadIdx.x;
    const int c   = tid & 127;
    const int kh  = tid >> 7;
    const int col = blockIdx.y * 128 + c;

    __shared__ float xs[8][512];
    __shared__ float red[8][136];

    for (int i = tid; i < 8 * 512; i += 256) {
        const int b = i >> 9, k = i & 511;
        xs[b][k] = x[((size_t)b * LL + LS + n) * Dd + k];
    }
    __syncthreads();

    const float* wp = nw + (size_t)n * Dd * Dd + col;
    float acc[8] = {};
    const int kbeg = kh * 256;
    for (int k = kbeg; k < kbeg + 256; k += 16) {
        float w[16];
        #pragma unroll
        for (int u = 0; u < 16; u++) w[u] = wp[(size_t)(k + u) * Dd];
        #pragma unroll
        for (int u = 0; u < 16; u++) {
            #pragma unroll
            for (int b = 0; b < 8; b++) acc[b] += xs[b][k + u] * w[u];
        }
    }
    if (kh == 1) {
        #pragma unroll
        for (int b = 0; b < 8; b++) red[b][c] = acc[b];
    }
    __syncthreads();
    if (kh == 0) {
        const float bias = nb[(size_t)n * Dd + col];
        const int h = col >> 6, dd = col & 63;
        const int l = out_tok_off + n;
        #pragma unroll
        for (int b = 0; b < 8; b++)
            Out[(((size_t)b * Hh + h) * Lout + l) * HD + dd] = acc[b] + red[b][c] + bias;
    }
}

// ---------------------------------------------------------------------------
// Flash attention on tf32 MMAs. grid (9, 64), 128 threads (4 warps).
// Block: one (b,h), 64 query rows; K-tiles of 64 keys.
// Qs/Kt: [dim][row] stride 72; Vt: [dim][key] stride 68 (conflict-free frags).
// P -> A-fragment conversion via intra-quad shuffles (no smem round trip).
// ---------------------------------------------------------------------------
#define ATTN_SMEM ((64*72 + 64*72 + 64*68) * 4 + 64 * 4)

__global__ __launch_bounds__(128) void attn_tc(
    const float* __restrict__ Q, const float* __restrict__ K,
    const float* __restrict__ V, const int* __restrict__ pad_mask,
    float* __restrict__ Outp)
{
    extern __shared__ unsigned sm[];
    unsigned* Qs = sm;                    // [64 dims][72] rows
    unsigned* Kt = sm + 64 * 72;          // [64 dims][72] keys
    unsigned* Vt = Kt + 64 * 72;          // [64 dims][68] keys
    float* pads  = (float*)(Vt + 64 * 68);

    const int tid  = threadIdx.x;
    const int lane = tid & 31, warp = tid >> 5;
    const int g = lane >> 2, tg = lane & 3;
    const int bh = blockIdx.y, b = bh >> 3, h = bh & 7;
    const int q0 = blockIdx.x << 6;

    const float* Qp = Q + ((size_t)bh * LQ + q0) * HD;
    const float* Kp = K + (size_t)bh * LK * HD;
    const float* Vp = V + (size_t)bh * LK * HD;

    // load Q transposed + scaled + tf32
    {
        const int r = tid & 63, dg = (tid >> 6) << 2;
        #pragma unroll
        for (int i = 0; i < 8; i++) {
            const int d = dg + i * 8;
            float4 v = *(const float4*)(Qp + (size_t)r * HD + d);
            Qs[(d + 0) * 72 + r] = f2tf(v.x * 0.125f);
            Qs[(d + 1) * 72 + r] = f2tf(v.y * 0.125f);
            Qs[(d + 2) * 72 + r] = f2tf(v.z * 0.125f);
            Qs[(d + 3) * 72 + r] = f2tf(v.w * 0.125f);
        }
    }

    float o[8][4];
    #pragma unroll
    for (int nt = 0; nt < 8; nt++)
        #pragma unroll
        for (int j = 0; j < 4; j++) o[nt][j] = 0.f;
    float m_run[2] = {-1e30f, -1e30f};
    float l_run[2] = {0.f, 0.f};

    const int row0 = q0 + warp * 16 + g;      // rows row0, row0+8
    const int ntiles = min(LK >> 6, ((q0 + 63 + DELTA) >> 6) + 1);

    for (int kt = 0; kt < ntiles; kt++) {
        const int k0 = kt << 6;
        __syncthreads();
        {
            const int r = tid & 63, dg = (tid >> 6) << 2;
            #pragma unroll
            for (int i = 0; i < 8; i++) {
                const int d = dg + i * 8;
                float4 kv = *(const float4*)(Kp + (size_t)(k0 + r) * HD + d);
                float4 vv = *(const float4*)(Vp + (size_t)(k0 + r) * HD + d);
                Kt[(d + 0) * 72 + r] = f2tf(kv.x);
                Kt[(d + 1) * 72 + r] = f2tf(kv.y);
                Kt[(d + 2) * 72 + r] = f2tf(kv.z);
                Kt[(d + 3) * 72 + r] = f2tf(kv.w);
                Vt[(d + 0) * 68 + r] = f2tf(vv.x);
                Vt[(d + 1) * 68 + r] = f2tf(vv.y);
                Vt[(d + 2) * 68 + r] = f2tf(vv.z);
                Vt[(d + 3) * 68 + r] = f2tf(vv.w);
            }
            if (tid < 64) {
                const int jg = k0 + tid;
                pads[tid] = (jg >= LS) ? 1.f : (pad_mask[(size_t)b * LS + jg] ? 1.f : 0.f);
            }
        }
        __syncthreads();

        // ---- S = Q K^T ----
        float sc[8][4];
        #pragma unroll
        for (int nt = 0; nt < 8; nt++)
            #pragma unroll
            for (int j = 0; j < 4; j++) sc[nt][j] = 0.f;

        #pragma unroll
        for (int ks = 0; ks < 8; ks++) {
            unsigned a[4];
            const int mr = warp * 16;
            a[0] = Qs[(ks * 8 + tg) * 72 + mr + g];
            a[1] = Qs[(ks * 8 + tg) * 72 + mr + g + 8];
            a[2] = Qs[(ks * 8 + tg + 4) * 72 + mr + g];
            a[3] = Qs[(ks * 8 + tg + 4) * 72 + mr + g + 8];
            #pragma unroll
            for (int nt = 0; nt < 8; nt++) {
                unsigned bb[2];
                bb[0] = Kt[(ks * 8 + tg) * 72 + nt * 8 + g];
                bb[1] = Kt[(ks * 8 + tg + 4) * 72 + nt * 8 + g];
                mma8(sc[nt], a, bb);
            }
        }

        // ---- mask + online softmax ----
        float mx0 = -1e30f, mx1 = -1e30f;
        #pragma unroll
        for (int nt = 0; nt < 8; nt++) {
            const int cb = k0 + nt * 8 + 2 * tg;
            const float p0 = pads[nt * 8 + 2 * tg];
            const float p1 = pads[nt * 8 + 2 * tg + 1];
            if (cb     > row0 + DELTA     || p0 == 0.f) sc[nt][0] = -1e9f;
            if (cb + 1 > row0 + DELTA     || p1 == 0.f) sc[nt][1] = -1e9f;
            if (cb     > row0 + 8 + DELTA || p0 == 0.f) sc[nt][2] = -1e9f;
            if (cb + 1 > row0 + 8 + DELTA || p1 == 0.f) sc[nt][3] = -1e9f;
            mx0 = fmaxf(mx0, fmaxf(sc[nt][0], sc[nt][1]));
            mx1 = fmaxf(mx1, fmaxf(sc[nt][2], sc[nt][3]));
        }
        mx0 = fmaxf(mx0, __shfl_xor_sync(0xffffffffu, mx0, 1));
        mx0 = fmaxf(mx0, __shfl_xor_sync(0xffffffffu, mx0, 2));
        mx1 = fmaxf(mx1, __shfl_xor_sync(0xffffffffu, mx1, 1));
        mx1 = fmaxf(mx1, __shfl_xor_sync(0xffffffffu, mx1, 2));

        const float mn0 = fmaxf(m_run[0], mx0);
        const float mn1 = fmaxf(m_run[1], mx1);
        const float cr0 = __expf(m_run[0] - mn0);
        const float cr1 = __expf(m_run[1] - mn1);

        float ls0 = 0.f, ls1 = 0.f;
        #pragma unroll
        for (int nt = 0; nt < 8; nt++) {
            sc[nt][0] = __expf(sc[nt][0] - mn0); ls0 += sc[nt][0];
            sc[nt][1] = __expf(sc[nt][1] - mn0); ls0 += sc[nt][1];
            sc[nt][2] = __expf(sc[nt][2] - mn1); ls1 += sc[nt][2];
            sc[nt][3] = __expf(sc[nt][3] - mn1); ls1 += sc[nt][3];
        }
        ls0 += __shfl_xor_sync(0xffffffffu, ls0, 1);
        ls0 += __shfl_xor_sync(0xffffffffu, ls0, 2);
        ls1 += __shfl_xor_sync(0xffffffffu, ls1, 1);
        ls1 += __shfl_xor_sync(0xffffffffu, ls1, 2);

        l_run[0] = l_run[0] * cr0 + ls0;
        l_run[1] = l_run[1] * cr1 + ls1;
        m_run[0] = mn0; m_run[1] = mn1;

        #pragma unroll
        for (int nt = 0; nt < 8; nt++) {
            o[nt][0] *= cr0; o[nt][1] *= cr0;
            o[nt][2] *= cr1; o[nt][3] *= cr1;
        }

        // ---- O += P V ---- (P fragments via quad shuffles)
        #pragma unroll
        for (int ks = 0; ks < 8; ks++) {
            const int s0 = (lane & ~3) | (tg >> 1);
            const int s1 = s0 + 2;
            unsigned a[4];
            {
                float e0 = __shfl_sync(0xffffffffu, sc[ks][0], s0);
                float e1 = __shfl_sync(0xffffffffu, sc[ks][1], s0);
                a[0] = f2tf((tg & 1) ? e1 : e0);
                float e2 = __shfl_sync(0xffffffffu, sc[ks][2], s0);
                float e3 = __shfl_sync(0xffffffffu, sc[ks][3], s0);
                a[1] = f2tf((tg & 1) ? e3 : e2);
                float f0 = __shfl_sync(0xffffffffu, sc[ks][0], s1);
                float f1 = __shfl_sync(0xffffffffu, sc[ks][1], s1);
                a[2] = f2tf((tg & 1) ? f1 : f0);
                float f2v = __shfl_sync(0xffffffffu, sc[ks][2], s1);
                float f3v = __shfl_sync(0xffffffffu, sc[ks][3], s1);
                a[3] = f2tf((tg & 1) ? f3v : f2v);
            }
            #pragma unroll
            for (int nt = 0; nt < 8; nt++) {
                unsigned bb[2];
                bb[0] = Vt[(nt * 8 + g) * 68 + ks * 8 + tg];
                bb[1] = Vt[(nt * 8 + g) * 68 + ks * 8 + tg + 4];
                mma8(o[nt], a, bb);
            }
        }
    }

    const float inv0 = (l_run[0] > 0.f) ? 1.f / l_run[0] : 0.f;
    const float inv1 = (l_run[1] > 0.f) ? 1.f / l_run[1] : 0.f;
    float* op0 = Outp + ((size_t)b * LQ + row0) * Dd + h * HD;
    float* op1 = op0 + (size_t)8 * Dd;
    #pragma unroll
    for (int nt = 0; nt < 8; nt++) {
        const int dc = nt * 8 + 2 * tg;
        *(float2*)(op0 + dc) = make_float2(o[nt][0] * inv0, o[nt][1] * inv0);
        *(float2*)(op1 + dc) = make_float2(o[nt][2] * inv1, o[nt][3] * inv1);
    }
}

// ---------------------------------------------------------------------------
extern "C" void kernel_launch(void* const* d_in, const int* in_sizes, int n_in,
                              void* d_out, int out_size)
{
    const float* x        = (const float*)d_in[0];
    const int*   pad_mask = (const int*)  d_in[1];
    const float* wq_sw = (const float*)d_in[4];
    const float* wq_sb = (const float*)d_in[5];
    const float* wq_nw = (const float*)d_in[6];
    const float* wq_nb = (const float*)d_in[7];
    const float* wk_sw = (const float*)d_in[8];
    const float* wk_sb = (const float*)d_in[9];
    const float* wk_nw = (const float*)d_in[10];
    const float* wk_nb = (const float*)d_in[11];
    const float* wv_sw = (const float*)d_in[12];
    const float* wv_sb = (const float*)d_in[13];
    const float* wv_nw = (const float*)d_in[14];
    const float* wv_nb = (const float*)d_in[15];
    const float* out_w = (const float*)d_in[16];
    const float* out_b = (const float*)d_in[17];
    float* out = (float*)d_out;

    float *pQ, *pK, *pV, *pA;
    cudaGetSymbolAddress((void**)&pQ, g_Q);
    cudaGetSymbolAddress((void**)&pK, g_K);
    cudaGetSymbolAddress((void**)&pV, g_V);
    cudaGetSymbolAddress((void**)&pA, g_attn);

    // Shared-weight projections (split-tf32 tensor-core GEMM)
    gemm_tc<<<dim3(8, 128), 256>>>(x, wk_sw, wk_sb, pK, LS, 0, LL, 1, LK, 0);
    gemm_tc<<<dim3(8, 128), 256>>>(x, wv_sw, wv_sb, pV, LS, 0, LL, 1, LK, 0);
    gemm_tc<<<dim3(8, 32),  256>>>(x, wq_sw, wq_sb, pQ, LSO, LS - LSO, LL, 1, LQ, 0);

    // Per-token projections (bandwidth-bound)
    ns_proj<<<dim3(64, 4), 256>>>(x, wq_nw, wq_nb, pQ, LQ, LSO);
    ns_proj<<<dim3(64, 4), 256>>>(x, wk_nw, wk_nb, pK, LK, LS);
    ns_proj<<<dim3(64, 4), 256>>>(x, wv_nw, wv_nb, pV, LK, LS);

    // Flash attention (tf32 MMA)
    cudaFuncSetAttribute(attn_tc, cudaFuncAttributeMaxDynamicSharedMemorySize, ATTN_SMEM);
    attn_tc<<<dim3(LQ / 64, Bc * Hh), 128, ATTN_SMEM>>>(pQ, pK, pV, pad_mask, pA);

    // Output projection
    gemm_tc<<<dim3(8, 36), 256>>>(pA, out_w, out_b, out, LQ, 0, LQ, 0, 0, 0);
}

// round 3
// speedup vs baseline: 4.2391x; 1.3083x over previous
#include <cuda_runtime.h>
#include <cuda_bf16.h>
#include <math.h>

#define Bc   8
#define Hh   8
#define Dd   512
#define HD   64
#define LNS  64
#define LS   2048
#define LSO  512
#define LQ   (LSO + LNS)   // 576
#define LK   (LS + LNS)    // 2112
#define LL   (LS + LNS)
#define DELTA (LK - LQ)    // 1536

__device__ float g_Q[(size_t)Bc * Hh * LQ * HD];
__device__ float g_K[(size_t)Bc * Hh * LK * HD];
__device__ float g_V[(size_t)Bc * Hh * LK * HD];
__device__ float g_attn[(size_t)Bc * LQ * Dd];

// ---------------------------------------------------------------------------
// helpers
// ---------------------------------------------------------------------------
__device__ __forceinline__ unsigned f2tf(float f) {
    unsigned u;
    asm("cvt.rna.tf32.f32 %0, %1;" : "=r"(u) : "f"(f));
    return u;
}

__device__ __forceinline__ void mma8(float* c, const unsigned* a, const unsigned* b) {
    asm volatile(
        "mma.sync.aligned.m16n8k8.row.col.f32.tf32.tf32.f32 "
        "{%0,%1,%2,%3},{%4,%5,%6,%7},{%8,%9},{%0,%1,%2,%3};\n"
        : "+f"(c[0]), "+f"(c[1]), "+f"(c[2]), "+f"(c[3])
        : "r"(a[0]), "r"(a[1]), "r"(a[2]), "r"(a[3]), "r"(b[0]), "r"(b[1]));
}

__device__ __forceinline__ void mma16bf(float* c, const unsigned* a, const unsigned* b) {
    asm volatile(
        "mma.sync.aligned.m16n8k16.row.col.f32.bf16.bf16.f32 "
        "{%0,%1,%2,%3},{%4,%5,%6,%7},{%8,%9},{%0,%1,%2,%3};\n"
        : "+f"(c[0]), "+f"(c[1]), "+f"(c[2]), "+f"(c[3])
        : "r"(a[0]), "r"(a[1]), "r"(a[2]), "r"(a[3]), "r"(b[0]), "r"(b[1]));
}

// pack two floats to bf16x2 (f0 -> low, f1 -> high), round-to-nearest
__device__ __forceinline__ unsigned pack_bf2(float f0, float f1) {
    unsigned r;
    asm("cvt.rn.bf16x2.f32 %0, %1, %2;" : "=r"(r) : "f"(f1), "f"(f0));
    return r;
}

// ---------------------------------------------------------------------------
// Split-bf16 GEMM (hi*hi + lo*hi + hi*lo, ~1e-5 accurate)
// C[M,512] = gather(X) @ W[512,512] + bias. Tile 128x64xk32, 256 thr, 8 warps.
// ---------------------------------------------------------------------------
__global__ __launch_bounds__(256) void gemm_tc(
    const float* __restrict__ X, const float* __restrict__ W,
    const float* __restrict__ bias, float* __restrict__ Out,
    int bt, int tok_off, int Lx, int mode, int Lout, int out_tok_off)
{
    // k2 = k/2 index (packed pairs). k-step 32 -> k2 in [0,16)
    __shared__ unsigned Ah[16][136], Al[16][136];   // [k2][m]
    __shared__ unsigned Bh[16][72],  Bl[16][72];    // [k2][n]

    const int tid  = threadIdx.x;
    const int lane = tid & 31, warp = tid >> 5;
    const int wm = warp >> 1, wn = warp & 1;
    const int g  = lane >> 2, tg = lane & 3;
    const int m0 = blockIdx.y << 7, n0 = blockIdx.x << 6;

    // A loader: row am, 16 consecutive k starting at ak
    const int am = tid & 127;
    const int ak = (tid >> 7) << 4;          // 0 or 16
    const int gm = m0 + am;
    const float* xrow = X + ((size_t)(gm / bt) * Lx + tok_off + (gm % bt)) * (size_t)Dd;

    // B loader: k-pair kp, 4 n's
    const int kp = tid >> 4;                 // 0..15
    const int n4 = (tid & 15) << 2;
    const float* wptr = W + (size_t)(2 * kp) * Dd + n0 + n4;

    float acc[2][4][4];
    #pragma unroll
    for (int a = 0; a < 2; a++)
        #pragma unroll
        for (int b = 0; b < 4; b++)
            #pragma unroll
            for (int c = 0; c < 4; c++) acc[a][b][c] = 0.f;

    for (int k0 = 0; k0 < Dd; k0 += 32) {
        // --- load & split A (128 x 32) ---
        #pragma unroll
        for (int v = 0; v < 4; v++) {
            float4 x4 = *(const float4*)(xrow + k0 + ak + v * 4);
            unsigned h0 = pack_bf2(x4.x, x4.y);
            unsigned h1 = pack_bf2(x4.z, x4.w);
            float l0x = x4.x - __uint_as_float(h0 << 16);
            float l0y = x4.y - __uint_as_float(h0 & 0xffff0000u);
            float l1z = x4.z - __uint_as_float(h1 << 16);
            float l1w = x4.w - __uint_as_float(h1 & 0xffff0000u);
            const int k2 = (ak >> 1) + v * 2;
            Ah[k2][am]     = h0;
            Ah[k2 + 1][am] = h1;
            Al[k2][am]     = pack_bf2(l0x, l0y);
            Al[k2 + 1][am] = pack_bf2(l1z, l1w);
        }
        // --- load & split B (32 x 64) ---
        {
            float4 r0 = *(const float4*)(wptr + (size_t)k0 * Dd);
            float4 r1 = *(const float4*)(wptr + (size_t)(k0 + 1) * Dd);
            float f0[4] = {r0.x, r0.y, r0.z, r0.w};
            float f1[4] = {r1.x, r1.y, r1.z, r1.w};
            #pragma unroll
            for (int j = 0; j < 4; j++) {
                unsigned hp = pack_bf2(f0[j], f1[j]);
                float lo0 = f0[j] - __uint_as_float(hp << 16);
                float lo1 = f1[j] - __uint_as_float(hp & 0xffff0000u);
                Bh[kp][n4 + j] = hp;
                Bl[kp][n4 + j] = pack_bf2(lo0, lo1);
            }
        }
        __syncthreads();

        #pragma unroll
        for (int ks = 0; ks < 2; ks++) {
            const int kb = ks * 8;
            unsigned ah[2][4], al[2][4], bhf[4][2], blf[4][2];
            #pragma unroll
            for (int mt = 0; mt < 2; mt++) {
                const int mr = wm * 32 + mt * 16;
                ah[mt][0] = Ah[kb + tg][mr + g];
                ah[mt][1] = Ah[kb + tg][mr + g + 8];
                ah[mt][2] = Ah[kb + tg + 4][mr + g];
                ah[mt][3] = Ah[kb + tg + 4][mr + g + 8];
                al[mt][0] = Al[kb + tg][mr + g];
                al[mt][1] = Al[kb + tg][mr + g + 8];
                al[mt][2] = Al[kb + tg + 4][mr + g];
                al[mt][3] = Al[kb + tg + 4][mr + g + 8];
            }
            #pragma unroll
            for (int nt = 0; nt < 4; nt++) {
                const int nc = wn * 32 + nt * 8 + g;
                bhf[nt][0] = Bh[kb + tg][nc];
                bhf[nt][1] = Bh[kb + tg + 4][nc];
                blf[nt][0] = Bl[kb + tg][nc];
                blf[nt][1] = Bl[kb + tg + 4][nc];
            }
            #pragma unroll
            for (int mt = 0; mt < 2; mt++)
                #pragma unroll
                for (int nt = 0; nt < 4; nt++) {
                    mma16bf(acc[mt][nt], ah[mt], bhf[nt]);   // hi*hi
                    mma16bf(acc[mt][nt], al[mt], bhf[nt]);   // lo*hi
                    mma16bf(acc[mt][nt], ah[mt], blf[nt]);   // hi*lo
                }
        }
        __syncthreads();
    }

    #pragma unroll
    for (int mt = 0; mt < 2; mt++)
        #pragma unroll
        for (int j2 = 0; j2 < 2; j2++) {
            const int m = m0 + wm * 32 + mt * 16 + g + j2 * 8;
            const int b = m / bt, t = m % bt;
            #pragma unroll
            for (int nt = 0; nt < 4; nt++) {
                const int n = n0 + wn * 32 + nt * 8 + 2 * tg;
                const float c0 = acc[mt][nt][j2 * 2 + 0] + bias[n];
                const float c1 = acc[mt][nt][j2 * 2 + 1] + bias[n + 1];
                if (mode == 0) {
                    *(float2*)&Out[(size_t)m * Dd + n] = make_float2(c0, c1);
                } else {
                    const int h = n >> 6, dd = n & 63;
                    *(float2*)&Out[(((size_t)b * Hh + h) * Lout + out_tok_off + t) * HD + dd] =
                        make_float2(c0, c1);
                }
            }
        }
}

// ---------------------------------------------------------------------------
// Per-token projections. grid (64 tokens, 4 col-blocks of 128), 256 threads.
// Thread: 4 cols (one float4/row), k-split 8-way in block, 8 LDG.128 in flight.
// ---------------------------------------------------------------------------
__global__ __launch_bounds__(256) void ns_proj(
    const float* __restrict__ x, const float* __restrict__ nw,
    const float* __restrict__ nb, float* __restrict__ Out,
    int Lout, int out_tok_off)
{
    const int n    = blockIdx.x;
    const int tid  = threadIdx.x;
    const int cgrp = tid & 31;        // float4 col group: cols cgrp*4..+3 (of 128)
    const int kh   = tid >> 5;        // 0..7
    const int kbeg = kh * 64;
    const int colb = blockIdx.y * 128;

    __shared__ float xs[8][512];
    __shared__ float red[8][8][128];  // [kh][b][c]

    for (int i = tid; i < 8 * 512; i += 256) {
        const int b = i >> 9, k = i & 511;
        xs[b][k] = x[((size_t)b * LL + LS + n) * Dd + k];
    }
    __syncthreads();

    const float4* wp4 = (const float4*)(nw + (size_t)n * Dd * Dd) + (colb >> 2) + cgrp;

    float acc[8][4];
    #pragma unroll
    for (int b = 0; b < 8; b++)
        #pragma unroll
        for (int j = 0; j < 4; j++) acc[b][j] = 0.f;

    for (int k = 0; k < 64; k += 8) {
        float4 w[8];
        #pragma unroll
        for (int u = 0; u < 8; u++)
            w[u] = wp4[(size_t)(kbeg + k + u) * 128];
        #pragma unroll
        for (int u = 0; u < 8; u++) {
            #pragma unroll
            for (int b = 0; b < 8; b++) {
                const float s = xs[b][kbeg + k + u];
                acc[b][0] += s * w[u].x;
                acc[b][1] += s * w[u].y;
                acc[b][2] += s * w[u].z;
                acc[b][3] += s * w[u].w;
            }
        }
    }

    #pragma unroll
    for (int b = 0; b < 8; b++)
        *(float4*)&red[kh][b][cgrp * 4] =
            make_float4(acc[b][0], acc[b][1], acc[b][2], acc[b][3]);
    __syncthreads();

    for (int i = tid; i < 8 * 128; i += 256) {
        const int b = i >> 7, c = i & 127;
        float s = 0.f;
        #pragma unroll
        for (int k8 = 0; k8 < 8; k8++) s += red[k8][b][c];
        const int col = colb + c;
        const int h = col >> 6, dd = col & 63;
        Out[(((size_t)b * Hh + h) * Lout + out_tok_off + n) * HD + dd] =
            s + nb[(size_t)n * Dd + col];
    }
}

// ---------------------------------------------------------------------------
// Flash attention on tf32 MMAs (unchanged from R2).
// ---------------------------------------------------------------------------
#define ATTN_SMEM ((64*72 + 64*72 + 64*68) * 4 + 64 * 4)

__global__ __launch_bounds__(128) void attn_tc(
    const float* __restrict__ Q, const float* __restrict__ K,
    const float* __restrict__ V, const int* __restrict__ pad_mask,
    float* __restrict__ Outp)
{
    extern __shared__ unsigned sm[];
    unsigned* Qs = sm;
    unsigned* Kt = sm + 64 * 72;
    unsigned* Vt = Kt + 64 * 72;
    float* pads  = (float*)(Vt + 64 * 68);

    const int tid  = threadIdx.x;
    const int lane = tid & 31, warp = tid >> 5;
    const int g = lane >> 2, tg = lane & 3;
    const int bh = blockIdx.y, b = bh >> 3, h = bh & 7;
    const int q0 = blockIdx.x << 6;

    const float* Qp = Q + ((size_t)bh * LQ + q0) * HD;
    const float* Kp = K + (size_t)bh * LK * HD;
    const float* Vp = V + (size_t)bh * LK * HD;

    {
        const int r = tid & 63, dg = (tid >> 6) << 2;
        #pragma unroll
        for (int i = 0; i < 8; i++) {
            const int d = dg + i * 8;
            float4 v = *(const float4*)(Qp + (size_t)r * HD + d);
            Qs[(d + 0) * 72 + r] = f2tf(v.x * 0.125f);
            Qs[(d + 1) * 72 + r] = f2tf(v.y * 0.125f);
            Qs[(d + 2) * 72 + r] = f2tf(v.z * 0.125f);
            Qs[(d + 3) * 72 + r] = f2tf(v.w * 0.125f);
        }
    }

    float o[8][4];
    #pragma unroll
    for (int nt = 0; nt < 8; nt++)
        #pragma unroll
        for (int j = 0; j < 4; j++) o[nt][j] = 0.f;
    float m_run[2] = {-1e30f, -1e30f};
    float l_run[2] = {0.f, 0.f};

    const int row0 = q0 + warp * 16 + g;
    const int ntiles = min(LK >> 6, ((q0 + 63 + DELTA) >> 6) + 1);

    for (int kt = 0; kt < ntiles; kt++) {
        const int k0 = kt << 6;
        __syncthreads();
        {
            const int r = tid & 63, dg = (tid >> 6) << 2;
            #pragma unroll
            for (int i = 0; i < 8; i++) {
                const int d = dg + i * 8;
                float4 kv = *(const float4*)(Kp + (size_t)(k0 + r) * HD + d);
                float4 vv = *(const float4*)(Vp + (size_t)(k0 + r) * HD + d);
                Kt[(d + 0) * 72 + r] = f2tf(kv.x);
                Kt[(d + 1) * 72 + r] = f2tf(kv.y);
                Kt[(d + 2) * 72 + r] = f2tf(kv.z);
                Kt[(d + 3) * 72 + r] = f2tf(kv.w);
                Vt[(d + 0) * 68 + r] = f2tf(vv.x);
                Vt[(d + 1) * 68 + r] = f2tf(vv.y);
                Vt[(d + 2) * 68 + r] = f2tf(vv.z);
                Vt[(d + 3) * 68 + r] = f2tf(vv.w);
            }
            if (tid < 64) {
                const int jg = k0 + tid;
                pads[tid] = (jg >= LS) ? 1.f : (pad_mask[(size_t)b * LS + jg] ? 1.f : 0.f);
            }
        }
        __syncthreads();

        float sc[8][4];
        #pragma unroll
        for (int nt = 0; nt < 8; nt++)
            #pragma unroll
            for (int j = 0; j < 4; j++) sc[nt][j] = 0.f;

        #pragma unroll
        for (int ks = 0; ks < 8; ks++) {
            unsigned a[4];
            const int mr = warp * 16;
            a[0] = Qs[(ks * 8 + tg) * 72 + mr + g];
            a[1] = Qs[(ks * 8 + tg) * 72 + mr + g + 8];
            a[2] = Qs[(ks * 8 + tg + 4) * 72 + mr + g];
            a[3] = Qs[(ks * 8 + tg + 4) * 72 + mr + g + 8];
            #pragma unroll
            for (int nt = 0; nt < 8; nt++) {
                unsigned bb[2];
                bb[0] = Kt[(ks * 8 + tg) * 72 + nt * 8 + g];
                bb[1] = Kt[(ks * 8 + tg + 4) * 72 + nt * 8 + g];
                mma8(sc[nt], a, bb);
            }
        }

        float mx0 = -1e30f, mx1 = -1e30f;
        #pragma unroll
        for (int nt = 0; nt < 8; nt++) {
            const int cb = k0 + nt * 8 + 2 * tg;
            const float p0 = pads[nt * 8 + 2 * tg];
            const float p1 = pads[nt * 8 + 2 * tg + 1];
            if (cb     > row0 + DELTA     || p0 == 0.f) sc[nt][0] = -1e9f;
            if (cb + 1 > row0 + DELTA     || p1 == 0.f) sc[nt][1] = -1e9f;
            if (cb     > row0 + 8 + DELTA || p0 == 0.f) sc[nt][2] = -1e9f;
            if (cb + 1 > row0 + 8 + DELTA || p1 == 0.f) sc[nt][3] = -1e9f;
            mx0 = fmaxf(mx0, fmaxf(sc[nt][0], sc[nt][1]));
            mx1 = fmaxf(mx1, fmaxf(sc[nt][2], sc[nt][3]));
        }
        mx0 = fmaxf(mx0, __shfl_xor_sync(0xffffffffu, mx0, 1));
        mx0 = fmaxf(mx0, __shfl_xor_sync(0xffffffffu, mx0, 2));
        mx1 = fmaxf(mx1, __shfl_xor_sync(0xffffffffu, mx1, 1));
        mx1 = fmaxf(mx1, __shfl_xor_sync(0xffffffffu, mx1, 2));

        const float mn0 = fmaxf(m_run[0], mx0);
        const float mn1 = fmaxf(m_run[1], mx1);
        const float cr0 = __expf(m_run[0] - mn0);
        const float cr1 = __expf(m_run[1] - mn1);

        float ls0 = 0.f, ls1 = 0.f;
        #pragma unroll
        for (int nt = 0; nt < 8; nt++) {
            sc[nt][0] = __expf(sc[nt][0] - mn0); ls0 += sc[nt][0];
            sc[nt][1] = __expf(sc[nt][1] - mn0); ls0 += sc[nt][1];
            sc[nt][2] = __expf(sc[nt][2] - mn1); ls1 += sc[nt][2];
            sc[nt][3] = __expf(sc[nt][3] - mn1); ls1 += sc[nt][3];
        }
        ls0 += __shfl_xor_sync(0xffffffffu, ls0, 1);
        ls0 += __shfl_xor_sync(0xffffffffu, ls0, 2);
        ls1 += __shfl_xor_sync(0xffffffffu, ls1, 1);
        ls1 += __shfl_xor_sync(0xffffffffu, ls1, 2);

        l_run[0] = l_run[0] * cr0 + ls0;
        l_run[1] = l_run[1] * cr1 + ls1;
        m_run[0] = mn0; m_run[1] = mn1;

        #pragma unroll
        for (int nt = 0; nt < 8; nt++) {
            o[nt][0] *= cr0; o[nt][1] *= cr0;
            o[nt][2] *= cr1; o[nt][3] *= cr1;
        }

        #pragma unroll
        for (int ks = 0; ks < 8; ks++) {
            const int s0 = (lane & ~3) | (tg >> 1);
            const int s1 = s0 + 2;
            unsigned a[4];
            {
                float e0 = __shfl_sync(0xffffffffu, sc[ks][0], s0);
                float e1 = __shfl_sync(0xffffffffu, sc[ks][1], s0);
                a[0] = f2tf((tg & 1) ? e1 : e0);
                float e2 = __shfl_sync(0xffffffffu, sc[ks][2], s0);
                float e3 = __shfl_sync(0xffffffffu, sc[ks][3], s0);
                a[1] = f2tf((tg & 1) ? e3 : e2);
                float f0 = __shfl_sync(0xffffffffu, sc[ks][0], s1);
                float f1 = __shfl_sync(0xffffffffu, sc[ks][1], s1);
                a[2] = f2tf((tg & 1) ? f1 : f0);
                float f2v = __shfl_sync(0xffffffffu, sc[ks][2], s1);
                float f3v = __shfl_sync(0xffffffffu, sc[ks][3], s1);
                a[3] = f2tf((tg & 1) ? f3v : f2v);
            }
            #pragma unroll
            for (int nt = 0; nt < 8; nt++) {
                unsigned bb[2];
                bb[0] = Vt[(nt * 8 + g) * 68 + ks * 8 + tg];
                bb[1] = Vt[(nt * 8 + g) * 68 + ks * 8 + tg + 4];
                mma8(o[nt], a, bb);
            }
        }
    }

    const float inv0 = (l_run[0] > 0.f) ? 1.f / l_run[0] : 0.f;
    const float inv1 = (l_run[1] > 0.f) ? 1.f / l_run[1] : 0.f;
    float* op0 = Outp + ((size_t)b * LQ + row0) * Dd + h * HD;
    float* op1 = op0 + (size_t)8 * Dd;
    #pragma unroll
    for (int nt = 0; nt < 8; nt++) {
        const int dc = nt * 8 + 2 * tg;
        *(float2*)(op0 + dc) = make_float2(o[nt][0] * inv0, o[nt][1] * inv0);
        *(float2*)(op1 + dc) = make_float2(o[nt][2] * inv1, o[nt][3] * inv1);
    }
}

// ---------------------------------------------------------------------------
extern "C" void kernel_launch(void* const* d_in, const int* in_sizes, int n_in,
                              void* d_out, int out_size)
{
    const float* x        = (const float*)d_in[0];
    const int*   pad_mask = (const int*)  d_in[1];
    const float* wq_sw = (const float*)d_in[4];
    const float* wq_sb = (const float*)d_in[5];
    const float* wq_nw = (const float*)d_in[6];
    const float* wq_nb = (const float*)d_in[7];
    const float* wk_sw = (const float*)d_in[8];
    const float* wk_sb = (const float*)d_in[9];
    const float* wk_nw = (const float*)d_in[10];
    const float* wk_nb = (const float*)d_in[11];
    const float* wv_sw = (const float*)d_in[12];
    const float* wv_sb = (const float*)d_in[13];
    const float* wv_nw = (const float*)d_in[14];
    const float* wv_nb = (const float*)d_in[15];
    const float* out_w = (const float*)d_in[16];
    const float* out_b = (const float*)d_in[17];
    float* out = (float*)d_out;

    float *pQ, *pK, *pV, *pA;
    cudaGetSymbolAddress((void**)&pQ, g_Q);
    cudaGetSymbolAddress((void**)&pK, g_K);
    cudaGetSymbolAddress((void**)&pV, g_V);
    cudaGetSymbolAddress((void**)&pA, g_attn);

    gemm_tc<<<dim3(8, 128), 256>>>(x, wk_sw, wk_sb, pK, LS, 0, LL, 1, LK, 0);
    gemm_tc<<<dim3(8, 128), 256>>>(x, wv_sw, wv_sb, pV, LS, 0, LL, 1, LK, 0);
    gemm_tc<<<dim3(8, 32),  256>>>(x, wq_sw, wq_sb, pQ, LSO, LS - LSO, LL, 1, LQ, 0);

    ns_proj<<<dim3(64, 4), 256>>>(x, wq_nw, wq_nb, pQ, LQ, LSO);
    ns_proj<<<dim3(64, 4), 256>>>(x, wk_nw, wk_nb, pK, LK, LS);
    ns_proj<<<dim3(64, 4), 256>>>(x, wv_nw, wv_nb, pV, LK, LS);

    cudaFuncSetAttribute(attn_tc, cudaFuncAttributeMaxDynamicSharedMemorySize, ATTN_SMEM);
    attn_tc<<<dim3(LQ / 64, Bc * Hh), 128, ATTN_SMEM>>>(pQ, pK, pV, pad_mask, pA);

    gemm_tc<<<dim3(8, 36), 256>>>(pA, out_w, out_b, out, LQ, 0, LQ, 0, 0, 0);
}

// round 4
// speedup vs baseline: 4.6353x; 1.0935x over previous
#include <cuda_runtime.h>
#include <cuda_bf16.h>
#include <cstdint>
#include <math.h>

#define Bc   8
#define Hh   8
#define Dd   512
#define HD   64
#define LNS  64
#define LS   2048
#define LSO  512
#define LQ   (LSO + LNS)   // 576
#define LK   (LS + LNS)    // 2112
#define LL   (LS + LNS)
#define DELTA (LK - LQ)    // 1536

__device__ float g_Q[(size_t)Bc * Hh * LQ * HD];
__device__ float g_K[(size_t)Bc * Hh * LK * HD];
__device__ float g_V[(size_t)Bc * Hh * LK * HD];
__device__ float g_attn[(size_t)Bc * LQ * Dd];

// ---------------------------------------------------------------------------
// helpers
// ---------------------------------------------------------------------------
__device__ __forceinline__ void mma8(float* c, const unsigned* a, const unsigned* b) {
    asm volatile(
        "mma.sync.aligned.m16n8k8.row.col.f32.tf32.tf32.f32 "
        "{%0,%1,%2,%3},{%4,%5,%6,%7},{%8,%9},{%0,%1,%2,%3};\n"
        : "+f"(c[0]), "+f"(c[1]), "+f"(c[2]), "+f"(c[3])
        : "r"(a[0]), "r"(a[1]), "r"(a[2]), "r"(a[3]), "r"(b[0]), "r"(b[1]));
}

__device__ __forceinline__ void mma16bf(float* c, const unsigned* a, const unsigned* b) {
    asm volatile(
        "mma.sync.aligned.m16n8k16.row.col.f32.bf16.bf16.f32 "
        "{%0,%1,%2,%3},{%4,%5,%6,%7},{%8,%9},{%0,%1,%2,%3};\n"
        : "+f"(c[0]), "+f"(c[1]), "+f"(c[2]), "+f"(c[3])
        : "r"(a[0]), "r"(a[1]), "r"(a[2]), "r"(a[3]), "r"(b[0]), "r"(b[1]));
}

__device__ __forceinline__ unsigned pack_bf2(float f0, float f1) {
    unsigned r;
    asm("cvt.rn.bf16x2.f32 %0, %1, %2;" : "=r"(r) : "f"(f1), "f"(f0));
    return r;
}

__device__ __forceinline__ void cp16(uint32_t sdst, const void* gsrc) {
    asm volatile("cp.async.ca.shared.global [%0], [%1], 16;\n" :: "r"(sdst), "l"(gsrc));
}
__device__ __forceinline__ void cp_commit() {
    asm volatile("cp.async.commit_group;\n" ::: "memory");
}
__device__ __forceinline__ void cp_wait0() {
    asm volatile("cp.async.wait_group 0;\n" ::: "memory");
}

// ---------------------------------------------------------------------------
// Split-bf16 GEMM. z selects (W, bias, Out) pair (K/V fusion).
// ---------------------------------------------------------------------------
__global__ __launch_bounds__(256) void gemm_tc(
    const float* __restrict__ X,
    const float* __restrict__ W0, const float* __restrict__ bias0, float* __restrict__ Out0,
    const float* __restrict__ W1, const float* __restrict__ bias1, float* __restrict__ Out1,
    int bt, int tok_off, int Lx, int mode, int Lout, int out_tok_off)
{
    const float* W    = (blockIdx.z == 0) ? W0    : W1;
    const float* bias = (blockIdx.z == 0) ? bias0 : bias1;
    float*       Out  = (blockIdx.z == 0) ? Out0  : Out1;

    __shared__ unsigned Ah[16][136], Al[16][136];
    __shared__ unsigned Bh[16][72],  Bl[16][72];

    const int tid  = threadIdx.x;
    const int lane = tid & 31, warp = tid >> 5;
    const int wm = warp >> 1, wn = warp & 1;
    const int g  = lane >> 2, tg = lane & 3;
    const int m0 = blockIdx.y << 7, n0 = blockIdx.x << 6;

    const int am = tid & 127;
    const int ak = (tid >> 7) << 4;
    const int gm = m0 + am;
    const float* xrow = X + ((size_t)(gm / bt) * Lx + tok_off + (gm % bt)) * (size_t)Dd;

    const int kp = tid >> 4;
    const int n4 = (tid & 15) << 2;
    const float* wptr = W + (size_t)(2 * kp) * Dd + n0 + n4;

    float acc[2][4][4];
    #pragma unroll
    for (int a = 0; a < 2; a++)
        #pragma unroll
        for (int b = 0; b < 4; b++)
            #pragma unroll
            for (int c = 0; c < 4; c++) acc[a][b][c] = 0.f;

    for (int k0 = 0; k0 < Dd; k0 += 32) {
        #pragma unroll
        for (int v = 0; v < 4; v++) {
            float4 x4 = *(const float4*)(xrow + k0 + ak + v * 4);
            unsigned h0 = pack_bf2(x4.x, x4.y);
            unsigned h1 = pack_bf2(x4.z, x4.w);
            float l0x = x4.x - __uint_as_float(h0 << 16);
            float l0y = x4.y - __uint_as_float(h0 & 0xffff0000u);
            float l1z = x4.z - __uint_as_float(h1 << 16);
            float l1w = x4.w - __uint_as_float(h1 & 0xffff0000u);
            const int k2 = (ak >> 1) + v * 2;
            Ah[k2][am]     = h0;
            Ah[k2 + 1][am] = h1;
            Al[k2][am]     = pack_bf2(l0x, l0y);
            Al[k2 + 1][am] = pack_bf2(l1z, l1w);
        }
        {
            float4 r0 = *(const float4*)(wptr + (size_t)k0 * Dd);
            float4 r1 = *(const float4*)(wptr + (size_t)(k0 + 1) * Dd);
            float f0[4] = {r0.x, r0.y, r0.z, r0.w};
            float f1[4] = {r1.x, r1.y, r1.z, r1.w};
            #pragma unroll
            for (int j = 0; j < 4; j++) {
                unsigned hp = pack_bf2(f0[j], f1[j]);
                float lo0 = f0[j] - __uint_as_float(hp << 16);
                float lo1 = f1[j] - __uint_as_float(hp & 0xffff0000u);
                Bh[kp][n4 + j] = hp;
                Bl[kp][n4 + j] = pack_bf2(lo0, lo1);
            }
        }
        __syncthreads();

        #pragma unroll
        for (int ks = 0; ks < 2; ks++) {
            const int kb = ks * 8;
            unsigned ah[2][4], al[2][4], bhf[4][2], blf[4][2];
            #pragma unroll
            for (int mt = 0; mt < 2; mt++) {
                const int mr = wm * 32 + mt * 16;
                ah[mt][0] = Ah[kb + tg][mr + g];
                ah[mt][1] = Ah[kb + tg][mr + g + 8];
                ah[mt][2] = Ah[kb + tg + 4][mr + g];
                ah[mt][3] = Ah[kb + tg + 4][mr + g + 8];
                al[mt][0] = Al[kb + tg][mr + g];
                al[mt][1] = Al[kb + tg][mr + g + 8];
                al[mt][2] = Al[kb + tg + 4][mr + g];
                al[mt][3] = Al[kb + tg + 4][mr + g + 8];
            }
            #pragma unroll
            for (int nt = 0; nt < 4; nt++) {
                const int nc = wn * 32 + nt * 8 + g;
                bhf[nt][0] = Bh[kb + tg][nc];
                bhf[nt][1] = Bh[kb + tg + 4][nc];
                blf[nt][0] = Bl[kb + tg][nc];
                blf[nt][1] = Bl[kb + tg + 4][nc];
            }
            #pragma unroll
            for (int mt = 0; mt < 2; mt++)
                #pragma unroll
                for (int nt = 0; nt < 4; nt++) {
                    mma16bf(acc[mt][nt], ah[mt], bhf[nt]);
                    mma16bf(acc[mt][nt], al[mt], bhf[nt]);
                    mma16bf(acc[mt][nt], ah[mt], blf[nt]);
                }
        }
        __syncthreads();
    }

    #pragma unroll
    for (int mt = 0; mt < 2; mt++)
        #pragma unroll
        for (int j2 = 0; j2 < 2; j2++) {
            const int m = m0 + wm * 32 + mt * 16 + g + j2 * 8;
            const int b = m / bt, t = m % bt;
            #pragma unroll
            for (int nt = 0; nt < 4; nt++) {
                const int n = n0 + wn * 32 + nt * 8 + 2 * tg;
                const float c0 = acc[mt][nt][j2 * 2 + 0] + bias[n];
                const float c1 = acc[mt][nt][j2 * 2 + 1] + bias[n + 1];
                if (mode == 0) {
                    *(float2*)&Out[(size_t)m * Dd + n] = make_float2(c0, c1);
                } else {
                    const int h = n >> 6, dd = n & 63;
                    *(float2*)&Out[(((size_t)b * Hh + h) * Lout + out_tok_off + t) * HD + dd] =
                        make_float2(c0, c1);
                }
            }
        }
}

// ---------------------------------------------------------------------------
// Per-token projections (unchanged from R3).
// ---------------------------------------------------------------------------
__global__ __launch_bounds__(256) void ns_proj(
    const float* __restrict__ x, const float* __restrict__ nw,
    const float* __restrict__ nb, float* __restrict__ Out,
    int Lout, int out_tok_off)
{
    const int n    = blockIdx.x;
    const int tid  = threadIdx.x;
    const int cgrp = tid & 31;
    const int kh   = tid >> 5;
    const int kbeg = kh * 64;
    const int colb = blockIdx.y * 128;

    __shared__ float xs[8][512];
    __shared__ float red[8][8][128];

    for (int i = tid; i < 8 * 512; i += 256) {
        const int b = i >> 9, k = i & 511;
        xs[b][k] = x[((size_t)b * LL + LS + n) * Dd + k];
    }
    __syncthreads();

    const float4* wp4 = (const float4*)(nw + (size_t)n * Dd * Dd) + (colb >> 2) + cgrp;

    float acc[8][4];
    #pragma unroll
    for (int b = 0; b < 8; b++)
        #pragma unroll
        for (int j = 0; j < 4; j++) acc[b][j] = 0.f;

    for (int k = 0; k < 64; k += 8) {
        float4 w[8];
        #pragma unroll
        for (int u = 0; u < 8; u++)
            w[u] = wp4[(size_t)(kbeg + k + u) * 128];
        #pragma unroll
        for (int u = 0; u < 8; u++) {
            #pragma unroll
            for (int b = 0; b < 8; b++) {
                const float s = xs[b][kbeg + k + u];
                acc[b][0] += s * w[u].x;
                acc[b][1] += s * w[u].y;
                acc[b][2] += s * w[u].z;
                acc[b][3] += s * w[u].w;
            }
        }
    }

    #pragma unroll
    for (int b = 0; b < 8; b++)
        *(float4*)&red[kh][b][cgrp * 4] =
            make_float4(acc[b][0], acc[b][1], acc[b][2], acc[b][3]);
    __syncthreads();

    for (int i = tid; i < 8 * 128; i += 256) {
        const int b = i >> 7, c = i & 127;
        float s = 0.f;
        #pragma unroll
        for (int k8 = 0; k8 < 8; k8++) s += red[k8][b][c];
        const int col = colb + c;
        const int h = col >> 6, dd = col & 63;
        Out[(((size_t)b * Hh + h) * Lout + out_tok_off + n) * HD + dd] =
            s + nb[(size_t)n * Dd + col];
    }
}

// ---------------------------------------------------------------------------
// Flash attention v2: raw fp32 bits into tf32 MMA (rz), Q/K row-major + cp.async,
// V transposed raw. grid (9, 64), 128 threads.
// ---------------------------------------------------------------------------
#define ATTN_SMEM ((3 * 64 * 68 + 64) * 4)

__global__ __launch_bounds__(128) void attn_tc(
    const float* __restrict__ Q, const float* __restrict__ K,
    const float* __restrict__ V, const int* __restrict__ pad_mask,
    float* __restrict__ Outp)
{
    extern __shared__ float smf[];
    float* Qs = smf;                   // [64 rows][68] raw fp32
    float* Kt = smf + 64 * 68;         // [64 keys][68]
    float* Vt = Kt + 64 * 68;          // [64 dims][68] transposed
    float* pads = Vt + 64 * 68;

    const int tid  = threadIdx.x;
    const int lane = tid & 31, warp = tid >> 5;
    const int g = lane >> 2, tg = lane & 3;
    const int bh = blockIdx.y, b = bh >> 3, h = bh & 7;
    const int q0 = blockIdx.x << 6;

    const float* Qp = Q + ((size_t)bh * LQ + q0) * HD;
    const float* Kp = K + (size_t)bh * LK * HD;
    const float* Vp = V + (size_t)bh * LK * HD;

    const uint32_t qs_u = (uint32_t)__cvta_generic_to_shared(Qs);
    const uint32_t kt_u = (uint32_t)__cvta_generic_to_shared(Kt);

    // async-load Q tile (64 x 64 fp32, 16B chunks)
    #pragma unroll
    for (int i = 0; i < 8; i++) {
        const int idx = i * 128 + tid;
        const int r = idx >> 4, c = idx & 15;
        cp16(qs_u + r * 272 + c * 16, (const char*)Qp + (size_t)r * 256 + c * 16);
    }
    cp_commit();

    float o[8][4];
    #pragma unroll
    for (int nt = 0; nt < 8; nt++)
        #pragma unroll
        for (int j = 0; j < 4; j++) o[nt][j] = 0.f;
    float m_run[2] = {-1e30f, -1e30f};
    float l_run[2] = {0.f, 0.f};

    const int row0 = q0 + warp * 16 + g;
    const int ntiles = min(LK >> 6, ((q0 + 63 + DELTA) >> 6) + 1);
    const int mr = warp * 16;

    for (int kt = 0; kt < ntiles; kt++) {
        const int k0 = kt << 6;
        __syncthreads();
        // K tile via cp.async (row-major raw)
        #pragma unroll
        for (int i = 0; i < 8; i++) {
            const int idx = i * 128 + tid;
            const int r = idx >> 4, c = idx & 15;
            cp16(kt_u + r * 272 + c * 16,
                 (const char*)Kp + (size_t)(k0 + r) * 256 + c * 16);
        }
        cp_commit();
        // V tile transposed via LDG+STS (raw bits)
        {
            const int r = tid & 63, dg = (tid >> 6) << 2;
            #pragma unroll
            for (int i = 0; i < 8; i++) {
                const int d = dg + i * 8;
                float4 vv = *(const float4*)(Vp + (size_t)(k0 + r) * HD + d);
                Vt[(d + 0) * 68 + r] = vv.x;
                Vt[(d + 1) * 68 + r] = vv.y;
                Vt[(d + 2) * 68 + r] = vv.z;
                Vt[(d + 3) * 68 + r] = vv.w;
            }
            if (tid < 64) {
                const int jg = k0 + tid;
                pads[tid] = (jg >= LS) ? 1.f : (pad_mask[(size_t)b * LS + jg] ? 1.f : 0.f);
            }
        }
        cp_wait0();
        __syncthreads();

        // ---- S = Q K^T (raw-bit tf32) ----
        float sc[8][4];
        #pragma unroll
        for (int nt = 0; nt < 8; nt++)
            #pragma unroll
            for (int j = 0; j < 4; j++) sc[nt][j] = 0.f;

        #pragma unroll
        for (int ks = 0; ks < 8; ks++) {
            unsigned a[4];
            a[0] = __float_as_uint(Qs[(mr + g) * 68 + ks * 8 + tg]);
            a[1] = __float_as_uint(Qs[(mr + g + 8) * 68 + ks * 8 + tg]);
            a[2] = __float_as_uint(Qs[(mr + g) * 68 + ks * 8 + tg + 4]);
            a[3] = __float_as_uint(Qs[(mr + g + 8) * 68 + ks * 8 + tg + 4]);
            #pragma unroll
            for (int nt = 0; nt < 8; nt++) {
                unsigned bb[2];
                bb[0] = __float_as_uint(Kt[(nt * 8 + g) * 68 + ks * 8 + tg]);
                bb[1] = __float_as_uint(Kt[(nt * 8 + g) * 68 + ks * 8 + tg + 4]);
                mma8(sc[nt], a, bb);
            }
        }

        // ---- scale + mask + online softmax ----
        float mx0 = -1e30f, mx1 = -1e30f;
        #pragma unroll
        for (int nt = 0; nt < 8; nt++) {
            sc[nt][0] *= 0.125f; sc[nt][1] *= 0.125f;
            sc[nt][2] *= 0.125f; sc[nt][3] *= 0.125f;
            const int cb = k0 + nt * 8 + 2 * tg;
            const float p0 = pads[nt * 8 + 2 * tg];
            const float p1 = pads[nt * 8 + 2 * tg + 1];
            if (cb     > row0 + DELTA     || p0 == 0.f) sc[nt][0] = -1e9f;
            if (cb + 1 > row0 + DELTA     || p1 == 0.f) sc[nt][1] = -1e9f;
            if (cb     > row0 + 8 + DELTA || p0 == 0.f) sc[nt][2] = -1e9f;
            if (cb + 1 > row0 + 8 + DELTA || p1 == 0.f) sc[nt][3] = -1e9f;
            mx0 = fmaxf(mx0, fmaxf(sc[nt][0], sc[nt][1]));
            mx1 = fmaxf(mx1, fmaxf(sc[nt][2], sc[nt][3]));
        }
        mx0 = fmaxf(mx0, __shfl_xor_sync(0xffffffffu, mx0, 1));
        mx0 = fmaxf(mx0, __shfl_xor_sync(0xffffffffu, mx0, 2));
        mx1 = fmaxf(mx1, __shfl_xor_sync(0xffffffffu, mx1, 1));
        mx1 = fmaxf(mx1, __shfl_xor_sync(0xffffffffu, mx1, 2));

        const float mn0 = fmaxf(m_run[0], mx0);
        const float mn1 = fmaxf(m_run[1], mx1);
        const float cr0 = __expf(m_run[0] - mn0);
        const float cr1 = __expf(m_run[1] - mn1);

        float ls0 = 0.f, ls1 = 0.f;
        #pragma unroll
        for (int nt = 0; nt < 8; nt++) {
            sc[nt][0] = __expf(sc[nt][0] - mn0); ls0 += sc[nt][0];
            sc[nt][1] = __expf(sc[nt][1] - mn0); ls0 += sc[nt][1];
            sc[nt][2] = __expf(sc[nt][2] - mn1); ls1 += sc[nt][2];
            sc[nt][3] = __expf(sc[nt][3] - mn1); ls1 += sc[nt][3];
        }
        ls0 += __shfl_xor_sync(0xffffffffu, ls0, 1);
        ls0 += __shfl_xor_sync(0xffffffffu, ls0, 2);
        ls1 += __shfl_xor_sync(0xffffffffu, ls1, 1);
        ls1 += __shfl_xor_sync(0xffffffffu, ls1, 2);

        l_run[0] = l_run[0] * cr0 + ls0;
        l_run[1] = l_run[1] * cr1 + ls1;
        m_run[0] = mn0; m_run[1] = mn1;

        #pragma unroll
        for (int nt = 0; nt < 8; nt++) {
            o[nt][0] *= cr0; o[nt][1] *= cr0;
            o[nt][2] *= cr1; o[nt][3] *= cr1;
        }

        // ---- O += P V ---- (P fragments via quad shuffles, raw bits)
        #pragma unroll
        for (int ks = 0; ks < 8; ks++) {
            const int s0 = (lane & ~3) | (tg >> 1);
            const int s1 = s0 + 2;
            unsigned a[4];
            {
                float e0 = __shfl_sync(0xffffffffu, sc[ks][0], s0);
                float e1 = __shfl_sync(0xffffffffu, sc[ks][1], s0);
                a[0] = __float_as_uint((tg & 1) ? e1 : e0);
                float e2 = __shfl_sync(0xffffffffu, sc[ks][2], s0);
                float e3 = __shfl_sync(0xffffffffu, sc[ks][3], s0);
                a[1] = __float_as_uint((tg & 1) ? e3 : e2);
                float f0 = __shfl_sync(0xffffffffu, sc[ks][0], s1);
                float f1 = __shfl_sync(0xffffffffu, sc[ks][1], s1);
                a[2] = __float_as_uint((tg & 1) ? f1 : f0);
                float f2v = __shfl_sync(0xffffffffu, sc[ks][2], s1);
                float f3v = __shfl_sync(0xffffffffu, sc[ks][3], s1);
                a[3] = __float_as_uint((tg & 1) ? f3v : f2v);
            }
            #pragma unroll
            for (int nt = 0; nt < 8; nt++) {
                unsigned bb[2];
                bb[0] = __float_as_uint(Vt[(nt * 8 + g) * 68 + ks * 8 + tg]);
                bb[1] = __float_as_uint(Vt[(nt * 8 + g) * 68 + ks * 8 + tg + 4]);
                mma8(o[nt], a, bb);
            }
        }
    }

    const float inv0 = (l_run[0] > 0.f) ? 1.f / l_run[0] : 0.f;
    const float inv1 = (l_run[1] > 0.f) ? 1.f / l_run[1] : 0.f;
    float* op0 = Outp + ((size_t)b * LQ + row0) * Dd + h * HD;
    float* op1 = op0 + (size_t)8 * Dd;
    #pragma unroll
    for (int nt = 0; nt < 8; nt++) {
        const int dc = nt * 8 + 2 * tg;
        *(float2*)(op0 + dc) = make_float2(o[nt][0] * inv0, o[nt][1] * inv0);
        *(float2*)(op1 + dc) = make_float2(o[nt][2] * inv1, o[nt][3] * inv1);
    }
}

// ---------------------------------------------------------------------------
extern "C" void kernel_launch(void* const* d_in, const int* in_sizes, int n_in,
                              void* d_out, int out_size)
{
    const float* x        = (const float*)d_in[0];
    const int*   pad_mask = (const int*)  d_in[1];
    const float* wq_sw = (const float*)d_in[4];
    const float* wq_sb = (const float*)d_in[5];
    const float* wq_nw = (const float*)d_in[6];
    const float* wq_nb = (const float*)d_in[7];
    const float* wk_sw = (const float*)d_in[8];
    const float* wk_sb = (const float*)d_in[9];
    const float* wk_nw = (const float*)d_in[10];
    const float* wk_nb = (const float*)d_in[11];
    const float* wv_sw = (const float*)d_in[12];
    const float* wv_sb = (const float*)d_in[13];
    const float* wv_nw = (const float*)d_in[14];
    const float* wv_nb = (const float*)d_in[15];
    const float* out_w = (const float*)d_in[16];
    const float* out_b = (const float*)d_in[17];
    float* out = (float*)d_out;

    float *pQ, *pK, *pV, *pA;
    cudaGetSymbolAddress((void**)&pQ, g_Q);
    cudaGetSymbolAddress((void**)&pK, g_K);
    cudaGetSymbolAddress((void**)&pV, g_V);
    cudaGetSymbolAddress((void**)&pA, g_attn);

    // 1: fused K+V projection
    gemm_tc<<<dim3(8, 128, 2), 256>>>(x, wk_sw, wk_sb, pK, wv_sw, wv_sb, pV,
                                      LS, 0, LL, 1, LK, 0);
    // 2: Q projection
    gemm_tc<<<dim3(8, 32, 1), 256>>>(x, wq_sw, wq_sb, pQ, wq_sw, wq_sb, pQ,
                                     LSO, LS - LSO, LL, 1, LQ, 0);
    // 3-5: per-token projections
    ns_proj<<<dim3(64, 4), 256>>>(x, wq_nw, wq_nb, pQ, LQ, LSO);
    ns_proj<<<dim3(64, 4), 256>>>(x, wk_nw, wk_nb, pK, LK, LS);
    ns_proj<<<dim3(64, 4), 256>>>(x, wv_nw, wv_nb, pV, LK, LS);

    // 6: attention (profiled launch: -s 5 -c 1)
    cudaFuncSetAttribute(attn_tc, cudaFuncAttributeMaxDynamicSharedMemorySize, ATTN_SMEM);
    attn_tc<<<dim3(LQ / 64, Bc * Hh), 128, ATTN_SMEM>>>(pQ, pK, pV, pad_mask, pA);

    // 7: output projection
    gemm_tc<<<dim3(8, 36, 1), 256>>>(pA, out_w, out_b, out, out_w, out_b, out,
                                     LQ, 0, LQ, 0, 0, 0);
}